// round 16
// baseline (speedup 1.0000x reference)
#include <cuda_runtime.h>
#include <cuda_fp16.h>
#include <math.h>

#define NQ   16384   // B*N1
#define N1_  4096
#define N2_  1024
#define DS   128
#define DD   64
#define DCAT 192
#define DOUT 256
#define KI   8
#define KN   16

typedef unsigned long long ull;

// ---------------- scratch (device globals; no allocation allowed) ----------------
__device__ float g_xe [NQ*DS];
__device__ float g_x2i[NQ*DS];
__device__ float g_T1 [NQ*256];   // [A | Dpart]
__device__ float g_T2 [NQ*256];   // [KD | Vv]
__device__ float g_Dm [NQ*DS];
__device__ float g_VX [NQ*DS];
__device__ float g_cat[NQ*DCAT];
__device__ float g_WqW1[DS*DS];
__device__ float g_WkW1[DS*DS];
__device__ float g_Wc1[DS*256];
__device__ float g_Wc2[DS*256];
__device__ int   g_widx[NQ*KI];
__device__ float g_w   [NQ*KI];
__device__ int   g_nidx[NQ*KN];
__device__ float g_part[256*DOUT*2];
__device__ float g_scale[DOUT];
__device__ float g_shift[DOUT];
__device__ float g_kd16[NQ*4*KN];
__device__ int   g_ki16[NQ*4*KN];
__device__ float g_kd8 [NQ*2*KI];
__device__ int   g_ki8 [NQ*2*KI];

// ---------------- packed f32x2 helpers ----------------
__device__ __forceinline__ ull pack2(float x, float y)
{
    ull r;
    asm("mov.b64 %0, {%1, %2};" : "=l"(r) : "f"(x), "f"(y));
    return r;
}
__device__ __forceinline__ ull fma2(ull a, ull b, ull c)
{
    ull d;
    asm("fma.rn.f32x2 %0, %1, %2, %3;" : "=l"(d) : "l"(a), "l"(b), "l"(c));
    return d;
}
__device__ __forceinline__ float2 unpack2(ull v)
{
    float2 f;
    asm("mov.b64 {%0, %1}, %2;" : "=f"(f.x), "=f"(f.y) : "l"(v));
    return f;
}

#define MMA16816(D, A0, A1, A2, A3, B0, B1)                                     \
    asm volatile(                                                               \
        "mma.sync.aligned.m16n8k16.row.col.f32.f16.f16.f32 "                    \
        "{%0,%1,%2,%3}, {%4,%5,%6,%7}, {%8,%9}, {%0,%1,%2,%3};"                 \
        : "+f"((D)[0]), "+f"((D)[1]), "+f"((D)[2]), "+f"((D)[3])                \
        : "r"(A0), "r"(A1), "r"(A2), "r"(A3), "r"(B0), "r"(B1))

// ---------------- fp32 SGEMM with f32x2 inner (dense stage only) ----------------
__global__ __launch_bounds__(256) void sgemm(
    const float* __restrict__ Am, const float* __restrict__ Bm,
    const float* __restrict__ bias, float* __restrict__ Cm,
    int M, int N, int K, float alpha, int hasBias, int bnA)
{
    __shared__ __align__(16) float As[16*129];
    __shared__ __align__(16) float Bs[16*128];
    const int t  = threadIdx.x;
    const int tx = t & 15, ty = t >> 4;
    const int row0 = blockIdx.y * 128, col0 = blockIdx.x * 128;

    const int ar = t >> 2;
    const int af = (t & 3) * 4;

    ull acc2[8][4];
#pragma unroll
    for (int i = 0; i < 8; i++)
#pragma unroll
        for (int jp = 0; jp < 4; jp++) acc2[i][jp] = pack2(0.f, 0.f);

    for (int k0 = 0; k0 < K; k0 += 16) {
        float sc0 = 1.f, sc1 = 1.f, sc2 = 1.f, sc3 = 1.f;
        float sh0 = 0.f, sh1 = 0.f, sh2 = 0.f, sh3 = 0.f;
        if (bnA) {
            sc0 = g_scale[k0+af+0]; sh0 = g_shift[k0+af+0];
            sc1 = g_scale[k0+af+1]; sh1 = g_shift[k0+af+1];
            sc2 = g_scale[k0+af+2]; sh2 = g_shift[k0+af+2];
            sc3 = g_scale[k0+af+3]; sh3 = g_shift[k0+af+3];
        }
#pragma unroll
        for (int h = 0; h < 2; h++) {
            int r = ar + h*64;
            float4 v = *(const float4*)&Am[(long)(row0 + r)*K + k0 + af];
            if (bnA) {
                v.x = fmaf(v.x, sc0, sh0); v.x = v.x > 0.f ? v.x : 0.f;
                v.y = fmaf(v.y, sc1, sh1); v.y = v.y > 0.f ? v.y : 0.f;
                v.z = fmaf(v.z, sc2, sh2); v.z = v.z > 0.f ? v.z : 0.f;
                v.w = fmaf(v.w, sc3, sh3); v.w = v.w > 0.f ? v.w : 0.f;
            }
            As[(af+0)*129 + r] = v.x;
            As[(af+1)*129 + r] = v.y;
            As[(af+2)*129 + r] = v.z;
            As[(af+3)*129 + r] = v.w;
        }
        {
            const float4* src = (const float4*)&Bm[(long)(k0 + ty)*N + col0 + tx*8];
            *(float4*)&Bs[ty*128 + tx*8]     = src[0];
            *(float4*)&Bs[ty*128 + tx*8 + 4] = src[1];
        }
        __syncthreads();
#pragma unroll
        for (int kk = 0; kk < 16; kk++) {
            const ull* bp = (const ull*)&Bs[kk*128 + tx*8];
            ull b0 = bp[0], b1 = bp[1], b2v = bp[2], b3 = bp[3];
            const float* ap = &As[kk*129 + ty*8];
#pragma unroll
            for (int i = 0; i < 8; i++) {
                float av = ap[i];
                ull a2 = pack2(av, av);
                acc2[i][0] = fma2(a2, b0,  acc2[i][0]);
                acc2[i][1] = fma2(a2, b1,  acc2[i][1]);
                acc2[i][2] = fma2(a2, b2v, acc2[i][2]);
                acc2[i][3] = fma2(a2, b3,  acc2[i][3]);
            }
        }
        __syncthreads();
    }
#pragma unroll
    for (int i = 0; i < 8; i++) {
        int r = row0 + ty*8 + i;
#pragma unroll
        for (int jp = 0; jp < 4; jp++) {
            int c = col0 + tx*8 + jp*2;
            float2 v = unpack2(acc2[i][jp]);
            v.x *= alpha; v.y *= alpha;
            if (hasBias) { v.x += bias[c]; v.y += bias[c+1]; }
            *(float2*)&Cm[(long)r * N + c] = v;
        }
    }
}

// ------- split-fp16 tensor-core GEMM: C = A@B (+bias), fp32-accurate -------------
// M%128==0, N%128==0, K%16==0. bnA: relu(bn(.)) on A elements (channel = k).
#define AP 24
__global__ __launch_bounds__(256) void hgemm(
    const float* __restrict__ Am, const float* __restrict__ Bm,
    const float* __restrict__ bias, float* __restrict__ Cm,
    int M, int N, int K, int hasBias, int bnA)
{
    __shared__ __align__(16) __half Ash[2][128*AP];   // [hi/lo][r][k]
    __shared__ __align__(16) __half Bsh[2][128*AP];   // [hi/lo][c][k]
    const int t    = threadIdx.x;
    const int lane = t & 31, w = t >> 5;
    const int grp  = lane >> 2, qd = lane & 3;
    const int mw   = w & 3, nw = w >> 2;              // warp tile: 32 rows x 64 cols
    const int row0 = blockIdx.y * 128, col0 = blockIdx.x * 128;

    float d[2][8][4];
#pragma unroll
    for (int ms = 0; ms < 2; ms++)
#pragma unroll
        for (int ns = 0; ns < 8; ns++)
#pragma unroll
            for (int j = 0; j < 4; j++) d[ms][ns][j] = 0.f;

    const int ar = t >> 1, akof = (t & 1) * 8;        // A: row, k-offset
    const int bc = t >> 1, bkof = (t & 1) * 8;        // B: col, k-offset

    for (int k0 = 0; k0 < K; k0 += 16) {
        __syncthreads();
        // A tile: load 8 floats, optional BN+ReLU, split into hi/lo halves
        {
            const float* src = &Am[(long)(row0 + ar)*K + k0 + akof];
            float4 v0 = *(const float4*)src;
            float4 v1 = *(const float4*)(src + 4);
            float v[8] = {v0.x, v0.y, v0.z, v0.w, v1.x, v1.y, v1.z, v1.w};
            if (bnA) {
#pragma unroll
                for (int i = 0; i < 8; i++) {
                    float x = fmaf(v[i], g_scale[k0+akof+i], g_shift[k0+akof+i]);
                    v[i] = x > 0.f ? x : 0.f;
                }
            }
#pragma unroll
            for (int i = 0; i < 8; i += 2) {
                __half hx = __float2half(v[i]);
                __half hy = __float2half(v[i+1]);
                __half lx = __float2half(v[i]   - __half2float(hx));
                __half ly = __float2half(v[i+1] - __half2float(hy));
                *(__half2*)&Ash[0][ar*AP + akof + i] = __halves2half2(hx, hy);
                *(__half2*)&Ash[1][ar*AP + akof + i] = __halves2half2(lx, ly);
            }
        }
        // B tile transposed: Bsh[c][k] = B[k][c], split hi/lo
        {
#pragma unroll
            for (int i = 0; i < 8; i += 2) {
                float x = Bm[(long)(k0 + bkof + i    )*N + col0 + bc];
                float y = Bm[(long)(k0 + bkof + i + 1)*N + col0 + bc];
                __half hx = __float2half(x), hy = __float2half(y);
                __half lx = __float2half(x - __half2float(hx));
                __half ly = __float2half(y - __half2float(hy));
                *(__half2*)&Bsh[0][bc*AP + bkof + i] = __halves2half2(hx, hy);
                *(__half2*)&Bsh[1][bc*AP + bkof + i] = __halves2half2(lx, ly);
            }
        }
        __syncthreads();
#pragma unroll
        for (int ms = 0; ms < 2; ms++) {
            int r0 = mw*32 + ms*16;
            unsigned ah0 = *(const unsigned*)&Ash[0][(r0+grp  )*AP + qd*2];
            unsigned ah1 = *(const unsigned*)&Ash[0][(r0+grp+8)*AP + qd*2];
            unsigned ah2 = *(const unsigned*)&Ash[0][(r0+grp  )*AP + qd*2 + 8];
            unsigned ah3 = *(const unsigned*)&Ash[0][(r0+grp+8)*AP + qd*2 + 8];
            unsigned al0 = *(const unsigned*)&Ash[1][(r0+grp  )*AP + qd*2];
            unsigned al1 = *(const unsigned*)&Ash[1][(r0+grp+8)*AP + qd*2];
            unsigned al2 = *(const unsigned*)&Ash[1][(r0+grp  )*AP + qd*2 + 8];
            unsigned al3 = *(const unsigned*)&Ash[1][(r0+grp+8)*AP + qd*2 + 8];
#pragma unroll
            for (int ns = 0; ns < 8; ns++) {
                int cb = nw*64 + ns*8 + grp;
                unsigned bh0 = *(const unsigned*)&Bsh[0][cb*AP + qd*2];
                unsigned bh1 = *(const unsigned*)&Bsh[0][cb*AP + qd*2 + 8];
                unsigned bl0 = *(const unsigned*)&Bsh[1][cb*AP + qd*2];
                unsigned bl1 = *(const unsigned*)&Bsh[1][cb*AP + qd*2 + 8];
                MMA16816(d[ms][ns], ah0, ah1, ah2, ah3, bh0, bh1);
                MMA16816(d[ms][ns], ah0, ah1, ah2, ah3, bl0, bl1);
                MMA16816(d[ms][ns], al0, al1, al2, al3, bh0, bh1);
            }
        }
    }
#pragma unroll
    for (int ms = 0; ms < 2; ms++) {
        int rA = row0 + mw*32 + ms*16 + grp;
        int rB = rA + 8;
#pragma unroll
        for (int ns = 0; ns < 8; ns++) {
            int c = col0 + nw*64 + ns*8 + qd*2;
            float bx = 0.f, by = 0.f;
            if (hasBias) { bx = bias[c]; by = bias[c+1]; }
            *(float2*)&Cm[(long)rA*N + c] = make_float2(d[ms][ns][0]+bx, d[ms][ns][1]+by);
            *(float2*)&Cm[(long)rB*N + c] = make_float2(d[ms][ns][2]+bx, d[ms][ns][3]+by);
        }
    }
}

// ---------------- weight products: WqW1, WkW1 in one launch ----------------
__global__ __launch_bounds__(128) void wprod(const float* __restrict__ Wq,
                                             const float* __restrict__ Wk,
                                             const float* __restrict__ W1)
{
    __shared__ float row[128];
    int b = blockIdx.x;
    const float* Wsrc = (b < 128) ? Wq : Wk;
    float* dst = (b < 128) ? g_WqW1 : g_WkW1;
    int r = b & 127;
    row[threadIdx.x] = Wsrc[r*128 + threadIdx.x];
    __syncthreads();
    int c = threadIdx.x;
    float acc = 0.f;
#pragma unroll 8
    for (int k = 0; k < 128; k++) acc = fmaf(row[k], W1[k*128 + c], acc);
    dst[r*128 + c] = acc;
}

__global__ void catw(const float* __restrict__ W1, const float* __restrict__ Wv)
{
    int i = blockIdx.x * 256 + threadIdx.x;
    if (i >= 128*256) return;
    int k = i >> 8, c = i & 255;
    g_Wc1[i] = (c < 128) ? g_WqW1[k*128 + c] : W1[k*128 + c - 128];
    g_Wc2[i] = (c < 128) ? g_WkW1[k*128 + c] : Wv[k*128 + c - 128];
}

// -- combine: D = T1[:,128:] - T2[:,:128]; VX = T2[:,128:] + relu(bn(xe_raw)) ----------
__global__ void combine()
{
    int i = blockIdx.x * 256 + threadIdx.x;
    if (i >= NQ*32) return;
    int q = i >> 5, c4 = i & 31;
    const float4* t1 = (const float4*)g_T1;
    const float4* t2 = (const float4*)g_T2;
    const float4* xe = (const float4*)g_xe;
    float4 dp = t1[q*64 + 32 + c4];
    float4 kd = t2[q*64 + c4];
    float4 vv = t2[q*64 + 32 + c4];
    float4 xv = xe[q*32 + c4];
    int c = c4 * 4;
    xv.x = fmaf(xv.x, g_scale[c+0], g_shift[c+0]); xv.x = xv.x > 0.f ? xv.x : 0.f;
    xv.y = fmaf(xv.y, g_scale[c+1], g_shift[c+1]); xv.y = xv.y > 0.f ? xv.y : 0.f;
    xv.z = fmaf(xv.z, g_scale[c+2], g_shift[c+2]); xv.z = xv.z > 0.f ? xv.z : 0.f;
    xv.w = fmaf(xv.w, g_scale[c+3], g_shift[c+3]); xv.w = xv.w > 0.f ? xv.w : 0.f;
    float4 d, v;
    d.x = dp.x - kd.x; d.y = dp.y - kd.y; d.z = dp.z - kd.z; d.w = dp.w - kd.w;
    v.x = vv.x + xv.x; v.y = vv.y + xv.y; v.z = vv.z + xv.z; v.w = vv.w + xv.w;
    ((float4*)g_Dm)[q*32 + c4] = d;
    ((float4*)g_VX)[q*32 + c4] = v;
}

// ---------------- Kahan helpers ----------------
__device__ __forceinline__ void kadd(float& s, float& cs, float v)
{
    float y = v - cs;
    float t = s + y;
    cs = (t - s) - y;
    s = t;
}

// ---------------- deterministic per-column BN stats (Kahan partials) ----------------
__global__ void colstats1(const float* __restrict__ X, int C, int rowsPerBlock, int R)
{
    int c = threadIdx.x, b = blockIdx.x;
    int r0 = b * rowsPerBlock, r1 = min(r0 + rowsPerBlock, R);
    float s = 0.f, cs = 0.f, s2 = 0.f, cs2 = 0.f;
    for (int r = r0; r < r1; r++) {
        float v = X[(long)r * C + c];
        kadd(s, cs, v);
        kadd(s2, cs2, v * v);
    }
    g_part[(b*C + c)*2]     = s;
    g_part[(b*C + c)*2 + 1] = s2;
}

__global__ void colstats2(int nb, int C, double invN,
                          const float* __restrict__ gamma, const float* __restrict__ beta)
{
    int c = threadIdx.x;
    if (c >= C) return;
    double s = 0.0, s2 = 0.0;
    for (int b = 0; b < nb; b++) {
        s  += (double)g_part[(b*C + c)*2];
        s2 += (double)g_part[(b*C + c)*2 + 1];
    }
    double m   = s * invN;
    double var = s2 * invN - m * m;
    float  sc  = gamma[c] * (float)rsqrt(var + 1e-5);
    g_scale[c] = sc;
    g_shift[c] = fmaf((float)(-m), sc, beta[c]);
}

__global__ void bnrelu4(float4* __restrict__ X, int total4, int cmask)
{
    int i = blockIdx.x * blockDim.x + threadIdx.x;
    if (i >= total4) return;
    int c = (i * 4) & cmask;
    float4 v = X[i];
    v.x = fmaf(v.x, g_scale[c+0], g_shift[c+0]);
    v.y = fmaf(v.y, g_scale[c+1], g_shift[c+1]);
    v.z = fmaf(v.z, g_scale[c+2], g_shift[c+2]);
    v.w = fmaf(v.w, g_scale[c+3], g_shift[c+3]);
    v.x = v.x > 0.f ? v.x : 0.f;
    v.y = v.y > 0.f ? v.y : 0.f;
    v.z = v.z > 0.f ? v.z : 0.f;
    v.w = v.w > 0.f ? v.w : 0.f;
    X[i] = v;
}

// ---------------- kNN partials: interpolation (top-8 per 512-candidate segment) --------
__global__ __launch_bounds__(128) void knn_interp_part(const float* __restrict__ p1,
                                                       const float* __restrict__ p2)
{
    __shared__ float4 sc[128];
    int q   = blockIdx.x * 128 + threadIdx.x;
    int seg = blockIdx.y;
    int bq  = q >> 12;
    int segbase = (bq << 10) + seg * 512;
    float qx = p1[q*3], qy = p1[q*3+1], qz = p1[q*3+2];
    float qq = qx*qx + qy*qy + qz*qz;
    float bd[KI]; int bi[KI];
#pragma unroll
    for (int k = 0; k < KI; k++) { bd[k] = 3.4e38f; bi[k] = 0; }

    for (int tile = 0; tile < 4; tile++) {
        int cg = segbase + tile*128 + threadIdx.x;
        float x = p2[cg*3], y = p2[cg*3+1], z = p2[cg*3+2];
        __syncthreads();
        sc[threadIdx.x] = make_float4(x, y, z, x*x + y*y + z*z);
        __syncthreads();
        for (int jj = 0; jj < 128; jj++) {
            float4 cp = sc[jj];
            float d2 = qq + cp.w - 2.f*(qx*cp.x + qy*cp.y + qz*cp.z);
            d2 = fmaxf(d2, 0.f);
            if (d2 < bd[KI-1]) {
                float cd = d2; int ci = segbase + tile*128 + jj;
#pragma unroll
                for (int s = 0; s < KI; s++) {
                    if (cd < bd[s]) {
                        float td = bd[s]; bd[s] = cd; cd = td;
                        int   ti = bi[s]; bi[s] = ci; ci = ti;
                    }
                }
            }
        }
    }
#pragma unroll
    for (int k = 0; k < KI; k++) {
        g_kd8[(q*2 + seg)*KI + k] = bd[k];
        g_ki8[(q*2 + seg)*KI + k] = bi[k];
    }
}

__global__ void knn_interp_merge()
{
    int q = blockIdx.x * 256 + threadIdx.x;
    float bd[KI]; int bi[KI];
#pragma unroll
    for (int k = 0; k < KI; k++) { bd[k] = 3.4e38f; bi[k] = 0; }
    for (int s = 0; s < 2*KI; s++) {
        float cd = g_kd8[q*2*KI + s];
        int   ci = g_ki8[q*2*KI + s];
        if (cd < bd[KI-1]) {
#pragma unroll
            for (int k = 0; k < KI; k++) {
                if (cd < bd[k]) {
                    float td = bd[k]; bd[k] = cd; cd = td;
                    int   ti = bi[k]; bi[k] = ci; ci = ti;
                }
            }
        }
    }
    float rec[KI], rs = 0.f;
#pragma unroll
    for (int k = 0; k < KI; k++) { rec[k] = 1.f / (sqrtf(bd[k]) + 1e-8f); rs += rec[k]; }
    float inv = 1.f / rs;
#pragma unroll
    for (int k = 0; k < KI; k++) {
        g_widx[q*KI + k] = bi[k];
        g_w  [q*KI + k] = rec[k] * inv;
    }
}

__global__ void interp_apply(const float* __restrict__ x2)
{
    int q = blockIdx.x, c = threadIdx.x;
    float acc = 0.f;
#pragma unroll
    for (int k = 0; k < KI; k++)
        acc = fmaf(g_w[q*KI + k], x2[(long)g_widx[q*KI + k]*DS + c], acc);
    g_x2i[(long)q*DS + c] = acc;
}

// ---------------- kNN partials: attention (top-16 per 1024-candidate segment) ----------
__global__ __launch_bounds__(128) void knn16_part(const float* __restrict__ p1)
{
    __shared__ float4 sc[128];
    int q   = blockIdx.x * 128 + threadIdx.x;
    int seg = blockIdx.y;
    int bq  = q >> 12;
    int segbase = (bq << 12) + seg * 1024;
    float qx = p1[q*3], qy = p1[q*3+1], qz = p1[q*3+2];
    float qq = qx*qx + qy*qy + qz*qz;
    float bd[KN]; int bi[KN];
#pragma unroll
    for (int k = 0; k < KN; k++) { bd[k] = 3.4e38f; bi[k] = 0; }

    for (int tile = 0; tile < 8; tile++) {
        int cg = segbase + tile*128 + threadIdx.x;
        float x = p1[cg*3], y = p1[cg*3+1], z = p1[cg*3+2];
        __syncthreads();
        sc[threadIdx.x] = make_float4(x, y, z, x*x + y*y + z*z);
        __syncthreads();
        for (int jj = 0; jj < 128; jj++) {
            float4 cp = sc[jj];
            float d2 = qq + cp.w - 2.f*(qx*cp.x + qy*cp.y + qz*cp.z);
            d2 = fmaxf(d2, 0.f);
            if (d2 < bd[KN-1]) {
                float cd = d2; int ci = segbase + tile*128 + jj;
#pragma unroll
                for (int s = 0; s < KN; s++) {
                    if (cd < bd[s]) {
                        float td = bd[s]; bd[s] = cd; cd = td;
                        int   ti = bi[s]; bi[s] = ci; ci = ti;
                    }
                }
            }
        }
    }
#pragma unroll
    for (int k = 0; k < KN; k++) {
        g_kd16[(q*4 + seg)*KN + k] = bd[k];
        g_ki16[(q*4 + seg)*KN + k] = bi[k];
    }
}

__global__ void knn16_merge()
{
    int q = blockIdx.x * 256 + threadIdx.x;
    float bd[KN]; int bi[KN];
#pragma unroll
    for (int k = 0; k < KN; k++) { bd[k] = 3.4e38f; bi[k] = 0; }
    for (int s = 0; s < 4*KN; s++) {
        float cd = g_kd16[q*4*KN + s];
        int   ci = g_ki16[q*4*KN + s];
        if (cd < bd[KN-1]) {
#pragma unroll
            for (int k = 0; k < KN; k++) {
                if (cd < bd[k]) {
                    float td = bd[k]; bd[k] = cd; cd = td;
                    int   ti = bi[k]; bi[k] = ci; ci = ti;
                }
            }
        }
    }
#pragma unroll
    for (int k = 0; k < KN; k++)
        g_nidx[q*KN + k] = bi[k];
}

// ------- stats over virtual h = A[n] + D[idx] + b1 (262144 x 128), plain dual chains ---
__global__ __launch_bounds__(128) void hstats1(const float* __restrict__ b1)
{
    int c = threadIdx.x, b = blockIdx.x;     // 256 blocks x 64 queries
    float b1c = b1[c];
    float se = 0.f, s2e = 0.f, so = 0.f, s2o = 0.f;
    for (int q = b*64; q < b*64 + 64; q++) {
        float a = g_T1[(long)q*256 + c] + b1c;
#pragma unroll 4
        for (int j = 0; j < KN; j += 2) {
            float v0 = a + g_Dm[(long)g_nidx[q*KN + j]  *DS + c];
            float v1 = a + g_Dm[(long)g_nidx[q*KN + j+1]*DS + c];
            se += v0; s2e = fmaf(v0, v0, s2e);
            so += v1; s2o = fmaf(v1, v1, s2o);
        }
    }
    g_part[(b*DS + c)*2]     = se + so;
    g_part[(b*DS + c)*2 + 1] = s2e + s2o;
}

// ---- fused attention: build h (BN+ReLU, fp16), h@W2 via mma.sync, softmax, aggregate ---
#define HP 136   // fp16 smem row stride
__global__ __launch_bounds__(256, 2) void attn_fused(
    const float* __restrict__ b1, const float* __restrict__ W2,
    float* __restrict__ cat)
{
    extern __shared__ __align__(16) char shm[];
    __half* Hsh  = (__half*)shm;                    // [r][k]  r=0..127, stride HP
    __half* W2sh = (__half*)(shm + 128*HP*2);       // [cc][k] stride HP (W2 transposed)
    int*    sidx = (int*)(shm + 2*128*HP*2);        // [128]

    const int t    = threadIdx.x;
    const int blk  = blockIdx.x;
    const int w    = t >> 5;
    const int lane = t & 31;
    const int grp  = lane >> 2;
    const int qd   = lane & 3;

    if (t < 128) sidx[t] = g_nidx[blk*128 + t];
    __syncthreads();

#pragma unroll 8
    for (int i = 0; i < 64; i++) {
        int L = t + i * 256;
        int k = L >> 7, cc = L & 127;
        W2sh[cc*HP + k] = __float2half(W2[L]);
    }
#pragma unroll 4
    for (int i = 0; i < 64; i++) {
        int L = t + i * 256;
        int r = L >> 7, c = L & 127;
        int q = blk*8 + (r >> 4);
        float v = g_T1[(long)q*256 + c] + g_Dm[(long)sidx[r]*DS + c] + b1[c];
        v = fmaf(v, g_scale[c], g_shift[c]);
        Hsh[r*HP + c] = __float2half(v > 0.f ? v : 0.f);
    }
    __syncthreads();

    const int r0 = w * 16;
    float d[16][4];
#pragma unroll
    for (int nt = 0; nt < 16; nt++)
#pragma unroll
        for (int j = 0; j < 4; j++) d[nt][j] = 0.f;

#pragma unroll
    for (int kc = 0; kc < 8; kc++) {
        int kb = kc * 16;
        unsigned a0 = *(const unsigned*)&Hsh[(r0+grp  )*HP + kb + qd*2    ];
        unsigned a1 = *(const unsigned*)&Hsh[(r0+grp+8)*HP + kb + qd*2    ];
        unsigned a2 = *(const unsigned*)&Hsh[(r0+grp  )*HP + kb + qd*2 + 8];
        unsigned a3 = *(const unsigned*)&Hsh[(r0+grp+8)*HP + kb + qd*2 + 8];
#pragma unroll
        for (int nt = 0; nt < 16; nt++) {
            int col = nt*8 + grp;
            unsigned b0 = *(const unsigned*)&W2sh[col*HP + kb + qd*2    ];
            unsigned b1r = *(const unsigned*)&W2sh[col*HP + kb + qd*2 + 8];
            MMA16816(d[nt], a0, a1, a2, a3, b0, b1r);
        }
    }

    const int q    = blk*8 + w;
    const int rowA = sidx[w*16 + grp];
    const int rowB = sidx[w*16 + grp + 8];
#pragma unroll
    for (int nt = 0; nt < 16; nt++) {
        int c0 = nt*8 + qd*2;
        float m0 = fmaxf(d[nt][0], d[nt][2]);
        float m1 = fmaxf(d[nt][1], d[nt][3]);
#pragma unroll
        for (int off = 4; off <= 16; off <<= 1) {
            m0 = fmaxf(m0, __shfl_xor_sync(0xffffffffu, m0, off));
            m1 = fmaxf(m1, __shfl_xor_sync(0xffffffffu, m1, off));
        }
        float eA0 = expf(d[nt][0] - m0);
        float eA1 = expf(d[nt][1] - m1);
        float eB0 = expf(d[nt][2] - m0);
        float eB1 = expf(d[nt][3] - m1);
        float2 vA = *(const float2*)&g_VX[(long)rowA*DS + c0];
        float2 vB = *(const float2*)&g_VX[(long)rowB*DS + c0];
        float s0  = eA0 + eB0;
        float s1  = eA1 + eB1;
        float ws0 = eA0*vA.x + eB0*vB.x;
        float ws1 = eA1*vA.y + eB1*vB.y;
#pragma unroll
        for (int off = 4; off <= 16; off <<= 1) {
            s0  += __shfl_xor_sync(0xffffffffu, s0,  off);
            s1  += __shfl_xor_sync(0xffffffffu, s1,  off);
            ws0 += __shfl_xor_sync(0xffffffffu, ws0, off);
            ws1 += __shfl_xor_sync(0xffffffffu, ws1, off);
        }
        if (grp == 0) {
            cat[(long)q*DCAT + c0]     = ws0 / s0;
            cat[(long)q*DCAT + c0 + 1] = ws1 / s1;
        }
    }
}

// ---------------- misc elementwise ----------------
__global__ void copy_x1cat(const float* __restrict__ x1)
{
    int i = blockIdx.x * blockDim.x + threadIdx.x;
    if (i >= NQ*DD) return;
    int q = i >> 6, c = i & 63;
    g_cat[(long)q*DCAT + DS + c] = x1[i];
}

__global__ void tailwrite(const float* __restrict__ p1, const int* __restrict__ o1,
                          float* __restrict__ out, int writeO1)
{
    int i = blockIdx.x * blockDim.x + threadIdx.x;
    if (i < NQ*3) out[i] = p1[i];
    else if (writeO1 && i < NQ*3 + 4) out[NQ*3 + NQ*DOUT + (i - NQ*3)] = (float)o1[i - NQ*3];
}

// ---------------- host orchestration ----------------
static float* symf(const void* p) { return (float*)p; }

extern "C" void kernel_launch(void* const* d_in, const int* in_sizes, int n_in,
                              void* d_out, int out_size)
{
    int wi = 6;
    if (n_in >= 24 && in_sizes[6] == 1) wi = 7;
    const float* p1 = (const float*)d_in[0];
    const float* x1 = (const float*)d_in[1];
    const int*   o1 = (const int*)  d_in[2];
    const float* p2 = (const float*)d_in[3];
    const float* x2 = (const float*)d_in[4];
    const float* W_dense  = (const float*)d_in[wi + 0];
    const float* b_dense  = (const float*)d_in[wi + 1];
    const float* gd       = (const float*)d_in[wi + 2];
    const float* btd      = (const float*)d_in[wi + 3];
    const float* Wq       = (const float*)d_in[wi + 4];
    const float* Wk       = (const float*)d_in[wi + 5];
    const float* Wv       = (const float*)d_in[wi + 6];
    const float* W1       = (const float*)d_in[wi + 7];
    const float* b1       = (const float*)d_in[wi + 8];
    const float* g1       = (const float*)d_in[wi + 9];
    const float* bt1      = (const float*)d_in[wi + 10];
    const float* W2       = (const float*)d_in[wi + 11];
    const float* W_out    = (const float*)d_in[wi + 13];
    const float* b_out    = (const float*)d_in[wi + 14];
    const float* g_o      = (const float*)d_in[wi + 15];
    const float* bt_o     = (const float*)d_in[wi + 16];

    void *pxe, *px2i, *pT1, *pT2, *pWc1, *pWc2, *pcat;
    cudaGetSymbolAddress(&pxe,  g_xe);
    cudaGetSymbolAddress(&px2i, g_x2i);
    cudaGetSymbolAddress(&pT1,  g_T1);
    cudaGetSymbolAddress(&pT2,  g_T2);
    cudaGetSymbolAddress(&pWc1, g_Wc1);
    cudaGetSymbolAddress(&pWc2, g_Wc2);
    cudaGetSymbolAddress(&pcat, g_cat);

    float* out = (float*)d_out;
    int full  = (out_size >= NQ*3 + NQ*DOUT + 4) ? 1 : 0;
    int pOnly = (out_size == NQ*3 + NQ*DOUT) ? 1 : 0;
    float* outx = (full || pOnly) ? (out + NQ*3) : out;

    const int shAttn = 2*128*HP*2 + 128*4;
    cudaFuncSetAttribute(attn_fused, cudaFuncAttributeMaxDynamicSharedMemorySize, shAttn);

    dim3 g128(1, NQ/128);
    dim3 g256(2, NQ/128);

    // 0) weight precompute (no data deps)
    wprod<<<256, 128>>>(Wq, Wk, W1);
    catw<<<128, 256>>>(W1, Wv);

    // 1) dense_mlp GEMM -> xe (raw); BN params; BN applied lazily by consumers
    sgemm<<<g128, 256>>>(x1, W_dense, b_dense, symf(pxe), NQ, DS, DD, 1.f, 1, 0);
    colstats1<<<256, DS>>>(symf(pxe), DS, NQ/256, NQ);
    colstats2<<<1, DS>>>(256, DS, 1.0/NQ, gd, btd);

    // 2) inverse-distance kNN interpolation -> x2i
    knn_interp_part<<<dim3(NQ/128, 2), 128>>>(p1, p2);
    knn_interp_merge<<<NQ/256, 256>>>();
    interp_apply<<<NQ, DS>>>(x2);

    // 3) tensor-core projections: T1 = relu(bn(xe))@Wc1, T2 = x2i@Wc2; combine
    hgemm<<<g256, 256>>>(symf(pxe),  symf(pWc1), nullptr, symf(pT1), NQ, 256, DS, 0, 1);
    hgemm<<<g256, 256>>>(symf(px2i), symf(pWc2), nullptr, symf(pT2), NQ, 256, DS, 0, 0);
    combine<<<(NQ*32 + 255)/256, 256>>>();

    // 4) attention neighbors + h-BN stats
    knn16_part<<<dim3(NQ/128, 4), 128>>>(p1);
    knn16_merge<<<NQ/256, 256>>>();
    hstats1<<<256, DS>>>(b1);
    colstats2<<<1, DS>>>(256, DS, 1.0/((double)NQ*KN), g1, bt1);

    // 5) fused BN/ReLU + h@W2 (tensor-core mma) + softmax + aggregate -> g_cat[:, :128]
    copy_x1cat<<<(NQ*DD + 255)/256, 256>>>(x1);
    attn_fused<<<NQ/8, 256, shAttn>>>(b1, W2, symf(pcat));

    // 6) output mlp (tensor-core)
    hgemm<<<g256, 256>>>(symf(pcat), W_out, b_out, outx, NQ, DOUT, DCAT, 1, 0);
    colstats1<<<256, DOUT>>>(outx, DOUT, NQ/256, NQ);
    colstats2<<<1, DOUT>>>(256, DOUT, 1.0/NQ, g_o, bt_o);
    bnrelu4<<<(NQ*DOUT/4 + 255)/256, 256>>>((float4*)outx, NQ*DOUT/4, DOUT-1);

    // 7) tail: p1 copy + o1 as float
    if (full || pOnly)
        tailwrite<<<(NQ*3 + 4 + 255)/256, 256>>>(p1, o1, out, full);
}

// round 17
// speedup vs baseline: 1.4572x; 1.4572x over previous
#include <cuda_runtime.h>
#include <cuda_fp16.h>
#include <math.h>

#define NQ   16384   // B*N1
#define N1_  4096
#define N2_  1024
#define DS   128
#define DD   64
#define DCAT 192
#define DOUT 256
#define KI   8
#define KN   16

typedef unsigned long long ull;

// ---------------- scratch (device globals; no allocation allowed) ----------------
__device__ float g_xe [NQ*DS];
__device__ float g_x2i[NQ*DS];
__device__ float g_T1 [NQ*256];   // [A | Dpart]
__device__ float g_T2 [NQ*256];   // [KD | Vv]
__device__ float g_Dm [NQ*DS];
__device__ float g_VX [NQ*DS];
__device__ float g_cat[NQ*DCAT];
__device__ float g_Wc1[DS*256];
__device__ float g_Wc2[DS*256];
__device__ int   g_widx[NQ*KI];
__device__ float g_w   [NQ*KI];
__device__ int   g_nidx[NQ*KN];
__device__ float g_part[256*DOUT*2];
__device__ float g_scale[DOUT];
__device__ float g_shift[DOUT];
__device__ float g_kd16[NQ*4*KN];
__device__ int   g_ki16[NQ*4*KN];
__device__ float g_kd8 [NQ*2*KI];
__device__ int   g_ki8 [NQ*2*KI];

// ---------------- packed f32x2 helpers ----------------
__device__ __forceinline__ ull pack2(float x, float y)
{
    ull r;
    asm("mov.b64 %0, {%1, %2};" : "=l"(r) : "f"(x), "f"(y));
    return r;
}
__device__ __forceinline__ ull fma2(ull a, ull b, ull c)
{
    ull d;
    asm("fma.rn.f32x2 %0, %1, %2, %3;" : "=l"(d) : "l"(a), "l"(b), "l"(c));
    return d;
}
__device__ __forceinline__ float2 unpack2(ull v)
{
    float2 f;
    asm("mov.b64 {%0, %1}, %2;" : "=f"(f.x), "=f"(f.y) : "l"(v));
    return f;
}

#define MMA16816(D, A0, A1, A2, A3, B0, B1)                                     \
    asm volatile(                                                               \
        "mma.sync.aligned.m16n8k16.row.col.f32.f16.f16.f32 "                    \
        "{%0,%1,%2,%3}, {%4,%5,%6,%7}, {%8,%9}, {%0,%1,%2,%3};"                 \
        : "+f"((D)[0]), "+f"((D)[1]), "+f"((D)[2]), "+f"((D)[3])                \
        : "r"(A0), "r"(A1), "r"(A2), "r"(A3), "r"(B0), "r"(B1))

// ---------------- fp32 SGEMM with f32x2 inner: C = alpha*A@B (+bias) ----------------
// M%128==0, N%128==0, K%16==0. bnA!=0: apply relu(bn(.)) to A elements on load.
__global__ __launch_bounds__(256) void sgemm(
    const float* __restrict__ Am, const float* __restrict__ Bm,
    const float* __restrict__ bias, float* __restrict__ Cm,
    int M, int N, int K, float alpha, int hasBias, int bnA)
{
    __shared__ __align__(16) float As[16*129];
    __shared__ __align__(16) float Bs[16*128];
    const int t  = threadIdx.x;
    const int tx = t & 15, ty = t >> 4;
    const int row0 = blockIdx.y * 128, col0 = blockIdx.x * 128;

    const int ar = t >> 2;
    const int af = (t & 3) * 4;

    ull acc2[8][4];
#pragma unroll
    for (int i = 0; i < 8; i++)
#pragma unroll
        for (int jp = 0; jp < 4; jp++) acc2[i][jp] = pack2(0.f, 0.f);

    for (int k0 = 0; k0 < K; k0 += 16) {
        float sc0 = 1.f, sc1 = 1.f, sc2 = 1.f, sc3 = 1.f;
        float sh0 = 0.f, sh1 = 0.f, sh2 = 0.f, sh3 = 0.f;
        if (bnA) {
            sc0 = g_scale[k0+af+0]; sh0 = g_shift[k0+af+0];
            sc1 = g_scale[k0+af+1]; sh1 = g_shift[k0+af+1];
            sc2 = g_scale[k0+af+2]; sh2 = g_shift[k0+af+2];
            sc3 = g_scale[k0+af+3]; sh3 = g_shift[k0+af+3];
        }
#pragma unroll
        for (int h = 0; h < 2; h++) {
            int r = ar + h*64;
            float4 v = *(const float4*)&Am[(long)(row0 + r)*K + k0 + af];
            if (bnA) {
                v.x = fmaf(v.x, sc0, sh0); v.x = v.x > 0.f ? v.x : 0.f;
                v.y = fmaf(v.y, sc1, sh1); v.y = v.y > 0.f ? v.y : 0.f;
                v.z = fmaf(v.z, sc2, sh2); v.z = v.z > 0.f ? v.z : 0.f;
                v.w = fmaf(v.w, sc3, sh3); v.w = v.w > 0.f ? v.w : 0.f;
            }
            As[(af+0)*129 + r] = v.x;
            As[(af+1)*129 + r] = v.y;
            As[(af+2)*129 + r] = v.z;
            As[(af+3)*129 + r] = v.w;
        }
        {
            const float4* src = (const float4*)&Bm[(long)(k0 + ty)*N + col0 + tx*8];
            *(float4*)&Bs[ty*128 + tx*8]     = src[0];
            *(float4*)&Bs[ty*128 + tx*8 + 4] = src[1];
        }
        __syncthreads();
#pragma unroll
        for (int kk = 0; kk < 16; kk++) {
            const ull* bp = (const ull*)&Bs[kk*128 + tx*8];
            ull b0 = bp[0], b1 = bp[1], b2v = bp[2], b3 = bp[3];
            const float* ap = &As[kk*129 + ty*8];
#pragma unroll
            for (int i = 0; i < 8; i++) {
                float av = ap[i];
                ull a2 = pack2(av, av);
                acc2[i][0] = fma2(a2, b0,  acc2[i][0]);
                acc2[i][1] = fma2(a2, b1,  acc2[i][1]);
                acc2[i][2] = fma2(a2, b2v, acc2[i][2]);
                acc2[i][3] = fma2(a2, b3,  acc2[i][3]);
            }
        }
        __syncthreads();
    }
#pragma unroll
    for (int i = 0; i < 8; i++) {
        int r = row0 + ty*8 + i;
#pragma unroll
        for (int jp = 0; jp < 4; jp++) {
            int c = col0 + tx*8 + jp*2;
            float2 v = unpack2(acc2[i][jp]);
            v.x *= alpha; v.y *= alpha;
            if (hasBias) { v.x += bias[c]; v.y += bias[c+1]; }
            *(float2*)&Cm[(long)r * N + c] = v;
        }
    }
}

// ------- weight build: Wc1 = [Wq@W1 | W1], Wc2 = [Wk@W1 | Wv] in ONE launch --------
__global__ __launch_bounds__(128) void wprod(const float* __restrict__ Wq,
                                             const float* __restrict__ Wk,
                                             const float* __restrict__ W1,
                                             const float* __restrict__ Wv)
{
    __shared__ float row[128];
    int b = blockIdx.x;          // 0..511
    int r = b & 127;
    int c = threadIdx.x;
    if (b < 256) {
        const float* Wsrc = (b < 128) ? Wq : Wk;
        float* dst = (b < 128) ? g_Wc1 : g_Wc2;
        row[c] = Wsrc[r*128 + c];
        __syncthreads();
        float acc = 0.f;
#pragma unroll 8
        for (int k = 0; k < 128; k++) acc = fmaf(row[k], W1[k*128 + c], acc);
        dst[r*256 + c] = acc;
    } else if (b < 384) {
        g_Wc1[r*256 + 128 + c] = W1[r*128 + c];
    } else {
        g_Wc2[r*256 + 128 + c] = Wv[r*128 + c];
    }
}

// -- combine: D = T1[:,128:] - T2[:,:128]; VX = T2[:,128:] + relu(bn(xe_raw)) ----------
__global__ void combine()
{
    int i = blockIdx.x * 256 + threadIdx.x;
    if (i >= NQ*32) return;
    int q = i >> 5, c4 = i & 31;
    const float4* t1 = (const float4*)g_T1;
    const float4* t2 = (const float4*)g_T2;
    const float4* xe = (const float4*)g_xe;
    float4 dp = t1[q*64 + 32 + c4];
    float4 kd = t2[q*64 + c4];
    float4 vv = t2[q*64 + 32 + c4];
    float4 xv = xe[q*32 + c4];
    int c = c4 * 4;
    xv.x = fmaf(xv.x, g_scale[c+0], g_shift[c+0]); xv.x = xv.x > 0.f ? xv.x : 0.f;
    xv.y = fmaf(xv.y, g_scale[c+1], g_shift[c+1]); xv.y = xv.y > 0.f ? xv.y : 0.f;
    xv.z = fmaf(xv.z, g_scale[c+2], g_shift[c+2]); xv.z = xv.z > 0.f ? xv.z : 0.f;
    xv.w = fmaf(xv.w, g_scale[c+3], g_shift[c+3]); xv.w = xv.w > 0.f ? xv.w : 0.f;
    float4 d, v;
    d.x = dp.x - kd.x; d.y = dp.y - kd.y; d.z = dp.z - kd.z; d.w = dp.w - kd.w;
    v.x = vv.x + xv.x; v.y = vv.y + xv.y; v.z = vv.z + xv.z; v.w = vv.w + xv.w;
    ((float4*)g_Dm)[q*32 + c4] = d;
    ((float4*)g_VX)[q*32 + c4] = v;
}

// ---------------- Kahan helpers ----------------
__device__ __forceinline__ void kadd(float& s, float& cs, float v)
{
    float y = v - cs;
    float t = s + y;
    cs = (t - s) - y;
    s = t;
}

// ---------------- deterministic per-column BN stats (Kahan partials) ----------------
__global__ void colstats1(const float* __restrict__ X, int C, int rowsPerBlock, int R)
{
    int c = threadIdx.x, b = blockIdx.x;
    int r0 = b * rowsPerBlock, r1 = min(r0 + rowsPerBlock, R);
    float s = 0.f, cs = 0.f, s2 = 0.f, cs2 = 0.f;
    for (int r = r0; r < r1; r++) {
        float v = X[(long)r * C + c];
        kadd(s, cs, v);
        kadd(s2, cs2, v * v);
    }
    g_part[(b*C + c)*2]     = s;
    g_part[(b*C + c)*2 + 1] = s2;
}

__global__ void colstats2(int nb, int C, double invN,
                          const float* __restrict__ gamma, const float* __restrict__ beta)
{
    int c = threadIdx.x;
    if (c >= C) return;
    double s = 0.0, s2 = 0.0;
    for (int b = 0; b < nb; b++) {
        s  += (double)g_part[(b*C + c)*2];
        s2 += (double)g_part[(b*C + c)*2 + 1];
    }
    double m   = s * invN;
    double var = s2 * invN - m * m;
    float  sc  = gamma[c] * (float)rsqrt(var + 1e-5);
    g_scale[c] = sc;
    g_shift[c] = fmaf((float)(-m), sc, beta[c]);
}

__global__ void bnrelu4(float4* __restrict__ X, int total4, int cmask)
{
    int i = blockIdx.x * blockDim.x + threadIdx.x;
    if (i >= total4) return;
    int c = (i * 4) & cmask;
    float4 v = X[i];
    v.x = fmaf(v.x, g_scale[c+0], g_shift[c+0]);
    v.y = fmaf(v.y, g_scale[c+1], g_shift[c+1]);
    v.z = fmaf(v.z, g_scale[c+2], g_shift[c+2]);
    v.w = fmaf(v.w, g_scale[c+3], g_shift[c+3]);
    v.x = v.x > 0.f ? v.x : 0.f;
    v.y = v.y > 0.f ? v.y : 0.f;
    v.z = v.z > 0.f ? v.z : 0.f;
    v.w = v.w > 0.f ? v.w : 0.f;
    X[i] = v;
}

// ---------------- kNN partials: interpolation (top-8 per 512-candidate segment) --------
__global__ __launch_bounds__(128) void knn_interp_part(const float* __restrict__ p1,
                                                       const float* __restrict__ p2)
{
    __shared__ float4 sc[128];
    int q   = blockIdx.x * 128 + threadIdx.x;
    int seg = blockIdx.y;
    int bq  = q >> 12;
    int segbase = (bq << 10) + seg * 512;
    float qx = p1[q*3], qy = p1[q*3+1], qz = p1[q*3+2];
    float qq = qx*qx + qy*qy + qz*qz;
    float bd[KI]; int bi[KI];
#pragma unroll
    for (int k = 0; k < KI; k++) { bd[k] = 3.4e38f; bi[k] = 0; }

    for (int tile = 0; tile < 4; tile++) {
        int cg = segbase + tile*128 + threadIdx.x;
        float x = p2[cg*3], y = p2[cg*3+1], z = p2[cg*3+2];
        __syncthreads();
        sc[threadIdx.x] = make_float4(x, y, z, x*x + y*y + z*z);
        __syncthreads();
        for (int jj = 0; jj < 128; jj++) {
            float4 cp = sc[jj];
            float d2 = qq + cp.w - 2.f*(qx*cp.x + qy*cp.y + qz*cp.z);
            d2 = fmaxf(d2, 0.f);
            if (d2 < bd[KI-1]) {
                float cd = d2; int ci = segbase + tile*128 + jj;
#pragma unroll
                for (int s = 0; s < KI; s++) {
                    if (cd < bd[s]) {
                        float td = bd[s]; bd[s] = cd; cd = td;
                        int   ti = bi[s]; bi[s] = ci; ci = ti;
                    }
                }
            }
        }
    }
#pragma unroll
    for (int k = 0; k < KI; k++) {
        g_kd8[(q*2 + seg)*KI + k] = bd[k];
        g_ki8[(q*2 + seg)*KI + k] = bi[k];
    }
}

__global__ void knn_interp_merge()
{
    int q = blockIdx.x * 256 + threadIdx.x;
    float bd[KI]; int bi[KI];
#pragma unroll
    for (int k = 0; k < KI; k++) { bd[k] = 3.4e38f; bi[k] = 0; }
    for (int s = 0; s < 2*KI; s++) {
        float cd = g_kd8[q*2*KI + s];
        int   ci = g_ki8[q*2*KI + s];
        if (cd < bd[KI-1]) {
#pragma unroll
            for (int k = 0; k < KI; k++) {
                if (cd < bd[k]) {
                    float td = bd[k]; bd[k] = cd; cd = td;
                    int   ti = bi[k]; bi[k] = ci; ci = ti;
                }
            }
        }
    }
    float rec[KI], rs = 0.f;
#pragma unroll
    for (int k = 0; k < KI; k++) { rec[k] = 1.f / (sqrtf(bd[k]) + 1e-8f); rs += rec[k]; }
    float inv = 1.f / rs;
#pragma unroll
    for (int k = 0; k < KI; k++) {
        g_widx[q*KI + k] = bi[k];
        g_w  [q*KI + k] = rec[k] * inv;
    }
}

__global__ void interp_apply(const float* __restrict__ x2)
{
    int q = blockIdx.x, c = threadIdx.x;
    float acc = 0.f;
#pragma unroll
    for (int k = 0; k < KI; k++)
        acc = fmaf(g_w[q*KI + k], x2[(long)g_widx[q*KI + k]*DS + c], acc);
    g_x2i[(long)q*DS + c] = acc;
}

// ---------------- kNN partials: attention (top-16 per 1024-candidate segment) ----------
__global__ __launch_bounds__(128) void knn16_part(const float* __restrict__ p1)
{
    __shared__ float4 sc[128];
    int q   = blockIdx.x * 128 + threadIdx.x;
    int seg = blockIdx.y;
    int bq  = q >> 12;
    int segbase = (bq << 12) + seg * 1024;
    float qx = p1[q*3], qy = p1[q*3+1], qz = p1[q*3+2];
    float qq = qx*qx + qy*qy + qz*qz;
    float bd[KN]; int bi[KN];
#pragma unroll
    for (int k = 0; k < KN; k++) { bd[k] = 3.4e38f; bi[k] = 0; }

    for (int tile = 0; tile < 8; tile++) {
        int cg = segbase + tile*128 + threadIdx.x;
        float x = p1[cg*3], y = p1[cg*3+1], z = p1[cg*3+2];
        __syncthreads();
        sc[threadIdx.x] = make_float4(x, y, z, x*x + y*y + z*z);
        __syncthreads();
        for (int jj = 0; jj < 128; jj++) {
            float4 cp = sc[jj];
            float d2 = qq + cp.w - 2.f*(qx*cp.x + qy*cp.y + qz*cp.z);
            d2 = fmaxf(d2, 0.f);
            if (d2 < bd[KN-1]) {
                float cd = d2; int ci = segbase + tile*128 + jj;
#pragma unroll
                for (int s = 0; s < KN; s++) {
                    if (cd < bd[s]) {
                        float td = bd[s]; bd[s] = cd; cd = td;
                        int   ti = bi[s]; bi[s] = ci; ci = ti;
                    }
                }
            }
        }
    }
#pragma unroll
    for (int k = 0; k < KN; k++) {
        g_kd16[(q*4 + seg)*KN + k] = bd[k];
        g_ki16[(q*4 + seg)*KN + k] = bi[k];
    }
}

__global__ void knn16_merge()
{
    int q = blockIdx.x * 256 + threadIdx.x;
    float bd[KN]; int bi[KN];
#pragma unroll
    for (int k = 0; k < KN; k++) { bd[k] = 3.4e38f; bi[k] = 0; }
    for (int s = 0; s < 4*KN; s++) {
        float cd = g_kd16[q*4*KN + s];
        int   ci = g_ki16[q*4*KN + s];
        if (cd < bd[KN-1]) {
#pragma unroll
            for (int k = 0; k < KN; k++) {
                if (cd < bd[k]) {
                    float td = bd[k]; bd[k] = cd; cd = td;
                    int   ti = bi[k]; bi[k] = ci; ci = ti;
                }
            }
        }
    }
#pragma unroll
    for (int k = 0; k < KN; k++)
        g_nidx[q*KN + k] = bi[k];
}

// ------- stats over virtual h = A[n] + D[idx] + b1 (262144 x 128), plain dual chains ---
__global__ __launch_bounds__(128) void hstats1(const float* __restrict__ b1)
{
    int c = threadIdx.x, b = blockIdx.x;     // 256 blocks x 64 queries
    float b1c = b1[c];
    float se = 0.f, s2e = 0.f, so = 0.f, s2o = 0.f;
    for (int q = b*64; q < b*64 + 64; q++) {
        float a = g_T1[(long)q*256 + c] + b1c;
#pragma unroll 4
        for (int j = 0; j < KN; j += 2) {
            float v0 = a + g_Dm[(long)g_nidx[q*KN + j]  *DS + c];
            float v1 = a + g_Dm[(long)g_nidx[q*KN + j+1]*DS + c];
            se += v0; s2e = fmaf(v0, v0, s2e);
            so += v1; s2o = fmaf(v1, v1, s2o);
        }
    }
    g_part[(b*DS + c)*2]     = se + so;
    g_part[(b*DS + c)*2 + 1] = s2e + s2o;
}

// ---- fused attention: build h (BN+ReLU, fp16), h@W2 via mma.sync, softmax, aggregate ---
#define HP 136   // fp16 smem row stride
__global__ __launch_bounds__(256, 2) void attn_fused(
    const float* __restrict__ b1, const float* __restrict__ W2,
    float* __restrict__ cat)
{
    extern __shared__ __align__(16) char shm[];
    __half* Hsh  = (__half*)shm;                    // [r][k]  r=0..127, stride HP
    __half* W2sh = (__half*)(shm + 128*HP*2);       // [cc][k] stride HP (W2 transposed)
    int*    sidx = (int*)(shm + 2*128*HP*2);        // [128]

    const int t    = threadIdx.x;
    const int blk  = blockIdx.x;
    const int w    = t >> 5;
    const int lane = t & 31;
    const int grp  = lane >> 2;
    const int qd   = lane & 3;

    if (t < 128) sidx[t] = g_nidx[blk*128 + t];
    __syncthreads();

#pragma unroll 8
    for (int i = 0; i < 64; i++) {
        int L = t + i * 256;
        int k = L >> 7, cc = L & 127;
        W2sh[cc*HP + k] = __float2half(W2[L]);
    }
#pragma unroll 4
    for (int i = 0; i < 64; i++) {
        int L = t + i * 256;
        int r = L >> 7, c = L & 127;
        int q = blk*8 + (r >> 4);
        float v = g_T1[(long)q*256 + c] + g_Dm[(long)sidx[r]*DS + c] + b1[c];
        v = fmaf(v, g_scale[c], g_shift[c]);
        Hsh[r*HP + c] = __float2half(v > 0.f ? v : 0.f);
    }
    __syncthreads();

    const int r0 = w * 16;
    float d[16][4];
#pragma unroll
    for (int nt = 0; nt < 16; nt++)
#pragma unroll
        for (int j = 0; j < 4; j++) d[nt][j] = 0.f;

#pragma unroll
    for (int kc = 0; kc < 8; kc++) {
        int kb = kc * 16;
        unsigned a0 = *(const unsigned*)&Hsh[(r0+grp  )*HP + kb + qd*2    ];
        unsigned a1 = *(const unsigned*)&Hsh[(r0+grp+8)*HP + kb + qd*2    ];
        unsigned a2 = *(const unsigned*)&Hsh[(r0+grp  )*HP + kb + qd*2 + 8];
        unsigned a3 = *(const unsigned*)&Hsh[(r0+grp+8)*HP + kb + qd*2 + 8];
#pragma unroll
        for (int nt = 0; nt < 16; nt++) {
            int col = nt*8 + grp;
            unsigned b0 = *(const unsigned*)&W2sh[col*HP + kb + qd*2    ];
            unsigned b1r = *(const unsigned*)&W2sh[col*HP + kb + qd*2 + 8];
            MMA16816(d[nt], a0, a1, a2, a3, b0, b1r);
        }
    }

    const int q    = blk*8 + w;
    const int rowA = sidx[w*16 + grp];
    const int rowB = sidx[w*16 + grp + 8];
#pragma unroll
    for (int nt = 0; nt < 16; nt++) {
        int c0 = nt*8 + qd*2;
        float m0 = fmaxf(d[nt][0], d[nt][2]);
        float m1 = fmaxf(d[nt][1], d[nt][3]);
#pragma unroll
        for (int off = 4; off <= 16; off <<= 1) {
            m0 = fmaxf(m0, __shfl_xor_sync(0xffffffffu, m0, off));
            m1 = fmaxf(m1, __shfl_xor_sync(0xffffffffu, m1, off));
        }
        float eA0 = expf(d[nt][0] - m0);
        float eA1 = expf(d[nt][1] - m1);
        float eB0 = expf(d[nt][2] - m0);
        float eB1 = expf(d[nt][3] - m1);
        float2 vA = *(const float2*)&g_VX[(long)rowA*DS + c0];
        float2 vB = *(const float2*)&g_VX[(long)rowB*DS + c0];
        float s0  = eA0 + eB0;
        float s1  = eA1 + eB1;
        float ws0 = eA0*vA.x + eB0*vB.x;
        float ws1 = eA1*vA.y + eB1*vB.y;
#pragma unroll
        for (int off = 4; off <= 16; off <<= 1) {
            s0  += __shfl_xor_sync(0xffffffffu, s0,  off);
            s1  += __shfl_xor_sync(0xffffffffu, s1,  off);
            ws0 += __shfl_xor_sync(0xffffffffu, ws0, off);
            ws1 += __shfl_xor_sync(0xffffffffu, ws1, off);
        }
        if (grp == 0) {
            cat[(long)q*DCAT + c0]     = ws0 / s0;
            cat[(long)q*DCAT + c0 + 1] = ws1 / s1;
        }
    }
}

// ---------------- misc elementwise ----------------
__global__ void copy_x1cat(const float* __restrict__ x1)
{
    int i = blockIdx.x * blockDim.x + threadIdx.x;
    if (i >= NQ*DD) return;
    int q = i >> 6, c = i & 63;
    g_cat[(long)q*DCAT + DS + c] = x1[i];
}

__global__ void tailwrite(const float* __restrict__ p1, const int* __restrict__ o1,
                          float* __restrict__ out, int writeO1)
{
    int i = blockIdx.x * blockDim.x + threadIdx.x;
    if (i < NQ*3) out[i] = p1[i];
    else if (writeO1 && i < NQ*3 + 4) out[NQ*3 + NQ*DOUT + (i - NQ*3)] = (float)o1[i - NQ*3];
}

// ---------------- host orchestration ----------------
static float* symf(const void* p) { return (float*)p; }

extern "C" void kernel_launch(void* const* d_in, const int* in_sizes, int n_in,
                              void* d_out, int out_size)
{
    int wi = 6;
    if (n_in >= 24 && in_sizes[6] == 1) wi = 7;
    const float* p1 = (const float*)d_in[0];
    const float* x1 = (const float*)d_in[1];
    const int*   o1 = (const int*)  d_in[2];
    const float* p2 = (const float*)d_in[3];
    const float* x2 = (const float*)d_in[4];
    const float* W_dense  = (const float*)d_in[wi + 0];
    const float* b_dense  = (const float*)d_in[wi + 1];
    const float* gd       = (const float*)d_in[wi + 2];
    const float* btd      = (const float*)d_in[wi + 3];
    const float* Wq       = (const float*)d_in[wi + 4];
    const float* Wk       = (const float*)d_in[wi + 5];
    const float* Wv       = (const float*)d_in[wi + 6];
    const float* W1       = (const float*)d_in[wi + 7];
    const float* b1       = (const float*)d_in[wi + 8];
    const float* g1       = (const float*)d_in[wi + 9];
    const float* bt1      = (const float*)d_in[wi + 10];
    const float* W2       = (const float*)d_in[wi + 11];
    const float* W_out    = (const float*)d_in[wi + 13];
    const float* b_out    = (const float*)d_in[wi + 14];
    const float* g_o      = (const float*)d_in[wi + 15];
    const float* bt_o     = (const float*)d_in[wi + 16];

    void *pxe, *px2i, *pT1, *pT2, *pWc1, *pWc2, *pcat;
    cudaGetSymbolAddress(&pxe,  g_xe);
    cudaGetSymbolAddress(&px2i, g_x2i);
    cudaGetSymbolAddress(&pT1,  g_T1);
    cudaGetSymbolAddress(&pT2,  g_T2);
    cudaGetSymbolAddress(&pWc1, g_Wc1);
    cudaGetSymbolAddress(&pWc2, g_Wc2);
    cudaGetSymbolAddress(&pcat, g_cat);

    float* out = (float*)d_out;
    int full  = (out_size >= NQ*3 + NQ*DOUT + 4) ? 1 : 0;
    int pOnly = (out_size == NQ*3 + NQ*DOUT) ? 1 : 0;
    float* outx = (full || pOnly) ? (out + NQ*3) : out;

    const int shAttn = 2*128*HP*2 + 128*4;
    cudaFuncSetAttribute(attn_fused, cudaFuncAttributeMaxDynamicSharedMemorySize, shAttn);

    dim3 g128(1, NQ/128);
    dim3 g256(2, NQ/128);

    // 0) weight precompute (no data deps): Wc1/Wc2 built directly
    wprod<<<512, 128>>>(Wq, Wk, W1, Wv);

    // 1) dense_mlp GEMM -> xe (raw); BN params; BN applied lazily by consumers
    sgemm<<<g128, 256>>>(x1, W_dense, b_dense, symf(pxe), NQ, DS, DD, 1.f, 1, 0);
    colstats1<<<256, DS>>>(symf(pxe), DS, NQ/256, NQ);
    colstats2<<<1, DS>>>(256, DS, 1.0/NQ, gd, btd);

    // 2) inverse-distance kNN interpolation -> x2i
    knn_interp_part<<<dim3(NQ/128, 2), 128>>>(p1, p2);
    knn_interp_merge<<<NQ/256, 256>>>();
    interp_apply<<<NQ, DS>>>(x2);

    // 3) fused projections: T1 = relu(bn(xe))@Wc1 (BN in A-load), T2 = x2i@Wc2; combine
    sgemm<<<g256, 256>>>(symf(pxe),  symf(pWc1), nullptr, symf(pT1), NQ, 256, DS, 1.f, 0, 1);
    sgemm<<<g256, 256>>>(symf(px2i), symf(pWc2), nullptr, symf(pT2), NQ, 256, DS, 1.f, 0, 0);
    combine<<<(NQ*32 + 255)/256, 256>>>();

    // 4) attention neighbors + h-BN stats
    knn16_part<<<dim3(NQ/128, 4), 128>>>(p1);
    knn16_merge<<<NQ/256, 256>>>();
    hstats1<<<256, DS>>>(b1);
    colstats2<<<1, DS>>>(256, DS, 1.0/((double)NQ*KN), g1, bt1);

    // 5) fused BN/ReLU + h@W2 (tensor-core mma) + softmax + aggregate -> g_cat[:, :128]
    copy_x1cat<<<(NQ*DD + 255)/256, 256>>>(x1);
    attn_fused<<<NQ/8, 256, shAttn>>>(b1, W2, symf(pcat));

    // 6) output mlp
    sgemm<<<g256, 256>>>(symf(pcat), W_out, b_out, outx, NQ, DOUT, DCAT, 1.f, 1, 0);
    colstats1<<<256, DOUT>>>(outx, DOUT, NQ/256, NQ);
    colstats2<<<1, DOUT>>>(256, DOUT, 1.0/NQ, g_o, bt_o);
    bnrelu4<<<(NQ*DOUT/4 + 255)/256, 256>>>((float4*)outx, NQ*DOUT/4, DOUT-1);

    // 7) tail: p1 copy + o1 as float
    if (full || pOnly)
        tailwrite<<<(NQ*3 + 4 + 255)/256, 256>>>(p1, o1, out, full);
}